// round 1
// baseline (speedup 1.0000x reference)
#include <cuda_runtime.h>

#define BQ 8
#define TT 1024
#define CC 768
#define HH 12
#define DD 64
#define MR (BQ*TT)
#define N3 (3*CC)

// Scratch (allocation-free rule: __device__ globals)
__device__ float g_q[(size_t)BQ*HH*TT*DD];   // [B,H,T,D] pre-scaled
__device__ float g_k[(size_t)BQ*HH*TT*DD];   // [B,H,T,D] with rel' folded in
__device__ float g_v[(size_t)BQ*HH*TT*DD];   // [B,H,T,D]
__device__ float g_y[(size_t)BQ*TT*CC];      // [B,T,C] attention output

// ---------------------------------------------------------------------------
// QKV GEMM: [8192,768] x [768,2304] + bias, epilogue scatters to q/k/v buffers
// 128x128 tile, BK=8, 256 threads, 8x8 per thread (two 4x4 quads).
// ---------------------------------------------------------------------------
__global__ __launch_bounds__(256, 2) void qkv_gemm_kernel(
    const float* __restrict__ X, const float* __restrict__ W,
    const float* __restrict__ bias, const float* __restrict__ rel)
{
    __shared__ float As[8][128];
    __shared__ float Bs[8][128];
    const int n0 = blockIdx.x * 128;
    const int m0 = blockIdx.y * 128;
    const int tid = threadIdx.x;
    const int tx = tid & 15, ty = tid >> 4;
    const int arow = tid >> 1, ak = (tid & 1) * 4;
    const int brow = tid >> 5, bcol = (tid & 31) * 4;

    float acc[8][8];
#pragma unroll
    for (int i = 0; i < 8; i++)
#pragma unroll
        for (int j = 0; j < 8; j++) acc[i][j] = 0.f;

    const float* Ap = X + (size_t)(m0 + arow) * CC + ak;
    const float* Bp = W + (size_t)brow * N3 + n0 + bcol;

    for (int k0 = 0; k0 < CC; k0 += 8) {
        float4 av = *(const float4*)(Ap + k0);
        float4 bv = *(const float4*)(Bp + (size_t)k0 * N3);
        __syncthreads();
        As[ak + 0][arow] = av.x;
        As[ak + 1][arow] = av.y;
        As[ak + 2][arow] = av.z;
        As[ak + 3][arow] = av.w;
        *(float4*)&Bs[brow][bcol] = bv;
        __syncthreads();
#pragma unroll
        for (int kk = 0; kk < 8; kk++) {
            float4 a0 = *(const float4*)&As[kk][ty * 4];
            float4 a1 = *(const float4*)&As[kk][64 + ty * 4];
            float4 b0 = *(const float4*)&Bs[kk][tx * 4];
            float4 b1 = *(const float4*)&Bs[kk][64 + tx * 4];
            float ra[8] = {a0.x, a0.y, a0.z, a0.w, a1.x, a1.y, a1.z, a1.w};
            float rb[8] = {b0.x, b0.y, b0.z, b0.w, b1.x, b1.y, b1.z, b1.w};
#pragma unroll
            for (int i = 0; i < 8; i++)
#pragma unroll
                for (int j = 0; j < 8; j++)
                    acc[i][j] += ra[i] * rb[j];
        }
    }

    // Epilogue: whole block lies in exactly one of {q,k,v} (768 % 128 == 0).
    const int seg = n0 / CC;
#pragma unroll
    for (int iq = 0; iq < 2; iq++) {
#pragma unroll
        for (int i2 = 0; i2 < 4; i2++) {
            const int r = m0 + iq * 64 + ty * 4 + i2;
            const int bb = r >> 10, t = r & 1023;
#pragma unroll
            for (int jq = 0; jq < 2; jq++) {
                const int gc = n0 + jq * 64 + tx * 4;
                const int c = gc - seg * CC;
                const int h = c >> 6, d = c & 63;
                float4 v;
                v.x = acc[iq * 4 + i2][jq * 4 + 0] + bias[gc + 0];
                v.y = acc[iq * 4 + i2][jq * 4 + 1] + bias[gc + 1];
                v.z = acc[iq * 4 + i2][jq * 4 + 2] + bias[gc + 2];
                v.w = acc[iq * 4 + i2][jq * 4 + 3] + bias[gc + 3];
                float* dst;
                if (seg == 0) {
                    v.x *= 0.125f; v.y *= 0.125f; v.z *= 0.125f; v.w *= 0.125f;
                    dst = g_q;
                } else if (seg == 1) {
                    if (t > 0) {
                        float4 rv = *(const float4*)&rel[(size_t)(t - 1) * DD + d];
                        v.x += rv.x; v.y += rv.y; v.z += rv.z; v.w += rv.w;
                    }
                    dst = g_k;
                } else {
                    dst = g_v;
                }
                *(float4*)&dst[(((size_t)bb * HH + h) * TT + t) * DD + d] = v;
            }
        }
    }
}

// ---------------------------------------------------------------------------
// Causal flash attention, fp32. BR=BC=64, D=64, 256 threads (16x16),
// 4x4 register tiles. S computed transposed (St[j][i]) so P^T lands in smem
// with aligned float4 stores; PV GEMM then reads Pt rows directly.
// ---------------------------------------------------------------------------
struct FlashSmem {
    float Qt[64][68];    // Q^T: [d][i], padded for aligned float4 + bank spread
    float Kt[64][68];    // K^T: [d][j]
    float Vs[64][64];    // V:  [j][d]
    float Pt[64][64];    // P^T:[j][i]
    float red1[16][64];  // column max partials
    float red2[16][64];  // column sum partials
    float ms[64];        // running row max
    float ls[64];        // running row sum
    float fs[64];        // rescale factor this tile
};

__global__ __launch_bounds__(256, 2) void flash_kernel()
{
    extern __shared__ char smem_raw[];
    FlashSmem* S = reinterpret_cast<FlashSmem*>(smem_raw);

    const int it = gridDim.x - 1 - blockIdx.x;   // heaviest tiles first
    const int bh = blockIdx.y;
    const float* Qg = g_q + (size_t)bh * TT * DD;
    const float* Kg = g_k + (size_t)bh * TT * DD;
    const float* Vg = g_v + (size_t)bh * TT * DD;

    const int tid = threadIdx.x;
    const int tx = tid & 15, ty = tid >> 4;
    const int dg = tid & 15, jb = tid >> 4;   // transpose-loader mapping

    // Load Q tile transposed: Qt[d][i]. Each thread transposes a 4x4 block.
    {
        const float* qp = &Qg[(size_t)(it * 64 + jb * 4) * DD + dg * 4];
        float4 t0 = *(const float4*)(qp);
        float4 t1 = *(const float4*)(qp + DD);
        float4 t2 = *(const float4*)(qp + 2 * DD);
        float4 t3 = *(const float4*)(qp + 3 * DD);
        *(float4*)&S->Qt[dg * 4 + 0][jb * 4] = make_float4(t0.x, t1.x, t2.x, t3.x);
        *(float4*)&S->Qt[dg * 4 + 1][jb * 4] = make_float4(t0.y, t1.y, t2.y, t3.y);
        *(float4*)&S->Qt[dg * 4 + 2][jb * 4] = make_float4(t0.z, t1.z, t2.z, t3.z);
        *(float4*)&S->Qt[dg * 4 + 3][jb * 4] = make_float4(t0.w, t1.w, t2.w, t3.w);
    }
    if (tid < 64) { S->ms[tid] = -1e30f; S->ls[tid] = 0.f; }

    float o[4][4];
#pragma unroll
    for (int a = 0; a < 4; a++)
#pragma unroll
        for (int b = 0; b < 4; b++) o[a][b] = 0.f;
    __syncthreads();

    for (int jt = 0; jt <= it; jt++) {
        __syncthreads();  // previous tile's PV reads of Vs/Pt must finish
        // Load K tile transposed + V tile straight.
        {
            const float* kp = &Kg[(size_t)(jt * 64 + jb * 4) * DD + dg * 4];
            float4 t0 = *(const float4*)(kp);
            float4 t1 = *(const float4*)(kp + DD);
            float4 t2 = *(const float4*)(kp + 2 * DD);
            float4 t3 = *(const float4*)(kp + 3 * DD);
            *(float4*)&S->Kt[dg * 4 + 0][jb * 4] = make_float4(t0.x, t1.x, t2.x, t3.x);
            *(float4*)&S->Kt[dg * 4 + 1][jb * 4] = make_float4(t0.y, t1.y, t2.y, t3.y);
            *(float4*)&S->Kt[dg * 4 + 2][jb * 4] = make_float4(t0.z, t1.z, t2.z, t3.z);
            *(float4*)&S->Kt[dg * 4 + 3][jb * 4] = make_float4(t0.w, t1.w, t2.w, t3.w);
            const float* vp = &Vg[(size_t)(jt * 64 + jb * 4) * DD + dg * 4];
            *(float4*)&S->Vs[jb * 4 + 0][dg * 4] = *(const float4*)(vp);
            *(float4*)&S->Vs[jb * 4 + 1][dg * 4] = *(const float4*)(vp + DD);
            *(float4*)&S->Vs[jb * 4 + 2][dg * 4] = *(const float4*)(vp + 2 * DD);
            *(float4*)&S->Vs[jb * 4 + 3][dg * 4] = *(const float4*)(vp + 3 * DD);
        }
        __syncthreads();

        // St[j][i] = sum_d K[j][d] * Q[i][d];  j = ty*4+a, i = tx*4+b
        float st[4][4];
#pragma unroll
        for (int a = 0; a < 4; a++)
#pragma unroll
            for (int b = 0; b < 4; b++) st[a][b] = 0.f;
#pragma unroll 16
        for (int d = 0; d < 64; d++) {
            float4 rk = *(const float4*)&S->Kt[d][ty * 4];
            float4 rq = *(const float4*)&S->Qt[d][tx * 4];
            float ka[4] = {rk.x, rk.y, rk.z, rk.w};
            float qa[4] = {rq.x, rq.y, rq.z, rq.w};
#pragma unroll
            for (int a = 0; a < 4; a++)
#pragma unroll
                for (int b = 0; b < 4; b++)
                    st[a][b] += ka[a] * qa[b];
        }
        if (jt == it) {  // diagonal tile: mask j > i
#pragma unroll
            for (int a = 0; a < 4; a++)
#pragma unroll
                for (int b = 0; b < 4; b++)
                    if (ty * 4 + a > tx * 4 + b) st[a][b] = -1e30f;
        }

        // Column (per-i) max partials
#pragma unroll
        for (int b = 0; b < 4; b++) {
            float m = fmaxf(fmaxf(st[0][b], st[1][b]), fmaxf(st[2][b], st[3][b]));
            S->red1[ty][tx * 4 + b] = m;
        }
        __syncthreads();

        float mnew[4];
#pragma unroll
        for (int b = 0; b < 4; b++) {
            float m = S->ms[tx * 4 + b];
#pragma unroll
            for (int yy = 0; yy < 16; yy++)
                m = fmaxf(m, S->red1[yy][tx * 4 + b]);
            mnew[b] = m;
        }

        // p = exp(st - mnew); write P^T; accumulate column sums
        float lsum[4] = {0.f, 0.f, 0.f, 0.f};
#pragma unroll
        for (int a = 0; a < 4; a++) {
            float p0 = __expf(st[a][0] - mnew[0]);
            float p1 = __expf(st[a][1] - mnew[1]);
            float p2 = __expf(st[a][2] - mnew[2]);
            float p3 = __expf(st[a][3] - mnew[3]);
            lsum[0] += p0; lsum[1] += p1; lsum[2] += p2; lsum[3] += p3;
            *(float4*)&S->Pt[ty * 4 + a][tx * 4] = make_float4(p0, p1, p2, p3);
        }
#pragma unroll
        for (int b = 0; b < 4; b++)
            S->red2[ty][tx * 4 + b] = lsum[b];
        __syncthreads();

        if (ty == 0) {
#pragma unroll
            for (int b = 0; b < 4; b++) {
                const int i = tx * 4 + b;
                float s = 0.f;
#pragma unroll
                for (int yy = 0; yy < 16; yy++) s += S->red2[yy][i];
                float f = __expf(S->ms[i] - mnew[b]);
                S->ls[i] = S->ls[i] * f + s;
                S->fs[i] = f;
                S->ms[i] = mnew[b];
            }
        }
        __syncthreads();

        // Rescale O (rows i = ty*4+a) and accumulate P @ V
#pragma unroll
        for (int a = 0; a < 4; a++) {
            float f = S->fs[ty * 4 + a];
#pragma unroll
            for (int b = 0; b < 4; b++) o[a][b] *= f;
        }
#pragma unroll 16
        for (int j = 0; j < 64; j++) {
            float4 rp = *(const float4*)&S->Pt[j][ty * 4];
            float4 rv = *(const float4*)&S->Vs[j][tx * 4];
            float pa[4] = {rp.x, rp.y, rp.z, rp.w};
            float va[4] = {rv.x, rv.y, rv.z, rv.w};
#pragma unroll
            for (int a = 0; a < 4; a++)
#pragma unroll
                for (int b = 0; b < 4; b++)
                    o[a][b] += pa[a] * va[b];
        }
    }

    // Write out: y[b, t, h*64 + d]
    const int h = bh % HH, bb = bh / HH;
#pragma unroll
    for (int a = 0; a < 4; a++) {
        const int i = ty * 4 + a;
        const int tg = it * 64 + i;
        const float inv = 1.0f / S->ls[i];
        float4 ov = make_float4(o[a][0] * inv, o[a][1] * inv,
                                o[a][2] * inv, o[a][3] * inv);
        *(float4*)&g_y[((size_t)bb * TT + tg) * CC + h * DD + tx * 4] = ov;
    }
}

// ---------------------------------------------------------------------------
// Output projection: g_y[8192,768] x w_proj[768,768] + b_proj -> d_out
// ---------------------------------------------------------------------------
__global__ __launch_bounds__(256, 2) void proj_gemm_kernel(
    const float* __restrict__ W, const float* __restrict__ bias,
    float* __restrict__ out)
{
    __shared__ float As[8][128];
    __shared__ float Bs[8][128];
    const int n0 = blockIdx.x * 128;
    const int m0 = blockIdx.y * 128;
    const int tid = threadIdx.x;
    const int tx = tid & 15, ty = tid >> 4;
    const int arow = tid >> 1, ak = (tid & 1) * 4;
    const int brow = tid >> 5, bcol = (tid & 31) * 4;

    float acc[8][8];
#pragma unroll
    for (int i = 0; i < 8; i++)
#pragma unroll
        for (int j = 0; j < 8; j++) acc[i][j] = 0.f;

    const float* Ap = g_y + (size_t)(m0 + arow) * CC + ak;
    const float* Bp = W + (size_t)brow * CC + n0 + bcol;

    for (int k0 = 0; k0 < CC; k0 += 8) {
        float4 av = *(const float4*)(Ap + k0);
        float4 bv = *(const float4*)(Bp + (size_t)k0 * CC);
        __syncthreads();
        As[ak + 0][arow] = av.x;
        As[ak + 1][arow] = av.y;
        As[ak + 2][arow] = av.z;
        As[ak + 3][arow] = av.w;
        *(float4*)&Bs[brow][bcol] = bv;
        __syncthreads();
#pragma unroll
        for (int kk = 0; kk < 8; kk++) {
            float4 a0 = *(const float4*)&As[kk][ty * 4];
            float4 a1 = *(const float4*)&As[kk][64 + ty * 4];
            float4 b0 = *(const float4*)&Bs[kk][tx * 4];
            float4 b1 = *(const float4*)&Bs[kk][64 + tx * 4];
            float ra[8] = {a0.x, a0.y, a0.z, a0.w, a1.x, a1.y, a1.z, a1.w};
            float rb[8] = {b0.x, b0.y, b0.z, b0.w, b1.x, b1.y, b1.z, b1.w};
#pragma unroll
            for (int i = 0; i < 8; i++)
#pragma unroll
                for (int j = 0; j < 8; j++)
                    acc[i][j] += ra[i] * rb[j];
        }
    }

#pragma unroll
    for (int iq = 0; iq < 2; iq++) {
#pragma unroll
        for (int i2 = 0; i2 < 4; i2++) {
            const int r = m0 + iq * 64 + ty * 4 + i2;
#pragma unroll
            for (int jq = 0; jq < 2; jq++) {
                const int gc = n0 + jq * 64 + tx * 4;
                float4 v;
                v.x = acc[iq * 4 + i2][jq * 4 + 0] + bias[gc + 0];
                v.y = acc[iq * 4 + i2][jq * 4 + 1] + bias[gc + 1];
                v.z = acc[iq * 4 + i2][jq * 4 + 2] + bias[gc + 2];
                v.w = acc[iq * 4 + i2][jq * 4 + 3] + bias[gc + 3];
                *(float4*)&out[(size_t)r * CC + gc] = v;
            }
        }
    }
}

// ---------------------------------------------------------------------------
extern "C" void kernel_launch(void* const* d_in, const int* in_sizes, int n_in,
                              void* d_out, int out_size)
{
    const float* x      = (const float*)d_in[0];
    const float* w_attn = (const float*)d_in[1];
    const float* b_attn = (const float*)d_in[2];
    const float* w_proj = (const float*)d_in[3];
    const float* b_proj = (const float*)d_in[4];
    const float* rel    = (const float*)d_in[5];
    float* out = (float*)d_out;

    cudaFuncSetAttribute(flash_kernel,
                         cudaFuncAttributeMaxDynamicSharedMemorySize,
                         (int)sizeof(FlashSmem));

    qkv_gemm_kernel<<<dim3(N3 / 128, MR / 128), 256>>>(x, w_attn, b_attn, rel);
    flash_kernel<<<dim3(TT / 64, BQ * HH), 256, sizeof(FlashSmem)>>>();
    proj_gemm_kernel<<<dim3(CC / 128, MR / 128), 256>>>(w_proj, b_proj, out);
}

// round 3
// speedup vs baseline: 1.3152x; 1.3152x over previous
#include <cuda_runtime.h>
#include <cuda_bf16.h>
#include <cstdint>

#define BQ 8
#define TT 1024
#define CC 768
#define HH 12
#define DD 64
#define MR (BQ*TT)
#define N3 (3*CC)

// Scratch (allocation-free rule: __device__ globals)
__device__ float g_q[(size_t)BQ*HH*TT*DD];   // [B,H,T,D] pre-scaled
__device__ float g_k[(size_t)BQ*HH*TT*DD];   // [B,H,T,D] with rel' folded in
__device__ float g_v[(size_t)BQ*HH*TT*DD];   // [B,H,T,D]
__device__ float g_y[(size_t)BQ*TT*CC];      // [B,T,C] attention output

// ---------------------------------------------------------------------------
// mma.sync m16n8k16 bf16 -> f32 (HMMA; family-PTX safe, no tcgen05)
// ---------------------------------------------------------------------------
__device__ __forceinline__ void mma16816(float* d, const uint32_t* a, const uint32_t* b) {
    asm volatile(
        "mma.sync.aligned.m16n8k16.row.col.f32.bf16.bf16.f32 "
        "{%0,%1,%2,%3}, {%4,%5,%6,%7}, {%8,%9}, {%0,%1,%2,%3};\n"
        : "+f"(d[0]), "+f"(d[1]), "+f"(d[2]), "+f"(d[3])
        : "r"(a[0]), "r"(a[1]), "r"(a[2]), "r"(a[3]), "r"(b[0]), "r"(b[1]));
}

struct __align__(8) BF4 { __nv_bfloat16 a, b, c, d; };

__device__ __forceinline__ void cvt_split(float x, __nv_bfloat16& h, __nv_bfloat16& l) {
    h = __float2bfloat16(x);
    l = __float2bfloat16(x - __bfloat162float(h));
}

// ---------------------------------------------------------------------------
// Tensor-core GEMM: C[8192 x Ncols] = A[8192 x 768] * W[768 x Ncols] (+bias)
// bf16 split (hi+lo, 3 passes), fp32 accumulators in registers.
// mode 0: A = X, epilogue scatters q/k/v (scale q, fold rel' into k)
// mode 1: A = g_y, epilogue writes out
// Tile: BM=128, BN=128, BK=32. 256 threads = 8 warps (2m x 4n), warp 64x32.
// SMEM: A[128][40]bf16 hi+lo, Bt[128][40]bf16 hi+lo, double buffered (80 KB).
// Stride 40 (bf16) makes all fragment LDS.b32 loads bank-conflict-free.
// ---------------------------------------------------------------------------
#define PAD 40
#define A_MAT (128 * PAD)             // bf16 elements per matrix
#define STAGE_ELEMS (4 * A_MAT)       // Ahi, Alo, Bhi, Blo
#define GEMM_SMEM (2 * STAGE_ELEMS * 2)  // bytes

__global__ __launch_bounds__(256, 1) void tc_gemm_kernel(
    const float* __restrict__ A_in, const float* __restrict__ W,
    const float* __restrict__ bias, const float* __restrict__ rel,
    float* __restrict__ out, int ldw, int mode)
{
    extern __shared__ __nv_bfloat16 sm[];

    const float* A = (mode == 0) ? A_in : g_y;

    const int tid = threadIdx.x;
    const int wid = tid >> 5, lane = tid & 31;
    const int n0 = blockIdx.x * 128;
    const int m0 = blockIdx.y * 128;

    const int warp_m = wid & 1;        // 0..1 -> 64 rows each
    const int warp_n = wid >> 1;       // 0..3 -> 32 cols each
    const int lr = lane >> 2;          // 0..7
    const int lc = lane & 3;           // 0..3

    // Loader mappings
    const int am = tid >> 1;                 // A row in tile
    const int akq = (tid & 1) * 16;          // A k quarter base
    const int bk0 = (tid >> 5) * 4;          // B k block (0..28)
    const int bn0 = (tid & 31) * 4;          // B n block (0..124)

    const float* Ag = A + (size_t)(m0 + am) * CC + akq;
    const float* Wg = W + (size_t)bk0 * ldw + n0 + bn0;

    float acc[4][4][4];
#pragma unroll
    for (int i = 0; i < 4; i++)
#pragma unroll
        for (int j = 0; j < 4; j++)
#pragma unroll
            for (int r = 0; r < 4; r++) acc[i][j][r] = 0.f;

    // Prefetch registers
    float4 pa[4];
    float4 pb[4];

    auto load_global = [&](int k0) {
#pragma unroll
        for (int c = 0; c < 4; c++)
            pa[c] = *(const float4*)(Ag + k0 + c * 4);
#pragma unroll
        for (int i = 0; i < 4; i++)
            pb[i] = *(const float4*)(Wg + (size_t)(k0 + i) * ldw);
    };

    auto store_smem = [&](int s) {
        __nv_bfloat16* base = sm + s * STAGE_ELEMS;
        __nv_bfloat16* sAhi = base;
        __nv_bfloat16* sAlo = base + A_MAT;
        __nv_bfloat16* sBhi = base + 2 * A_MAT;
        __nv_bfloat16* sBlo = base + 3 * A_MAT;
#pragma unroll
        for (int c = 0; c < 4; c++) {
            BF4 h, l;
            cvt_split(pa[c].x, h.a, l.a);
            cvt_split(pa[c].y, h.b, l.b);
            cvt_split(pa[c].z, h.c, l.c);
            cvt_split(pa[c].w, h.d, l.d);
            const int off = am * PAD + akq + c * 4;
            *(BF4*)(sAhi + off) = h;
            *(BF4*)(sAlo + off) = l;
        }
        // transpose 4x4: pb[i] holds W[k0+i][n0..n0+3]
        float col[4][4] = {
            {pb[0].x, pb[1].x, pb[2].x, pb[3].x},
            {pb[0].y, pb[1].y, pb[2].y, pb[3].y},
            {pb[0].z, pb[1].z, pb[2].z, pb[3].z},
            {pb[0].w, pb[1].w, pb[2].w, pb[3].w}};
#pragma unroll
        for (int j = 0; j < 4; j++) {
            BF4 h, l;
            cvt_split(col[j][0], h.a, l.a);
            cvt_split(col[j][1], h.b, l.b);
            cvt_split(col[j][2], h.c, l.c);
            cvt_split(col[j][3], h.d, l.d);
            const int off = (bn0 + j) * PAD + bk0;
            *(BF4*)(sBhi + off) = h;
            *(BF4*)(sBlo + off) = l;
        }
    };

    load_global(0);
    store_smem(0);
    __syncthreads();

    const int arow0 = warp_m * 64 + lr;       // + mi*16 (+8)
    const int brow0 = warp_n * 32 + lr;       // + ni*8
    const int kcol0 = lc * 2;                 // + ks*16 (+8)

    for (int stage = 0; stage < 24; stage++) {
        if (stage < 23) load_global((stage + 1) * 32);

        const __nv_bfloat16* base = sm + (stage & 1) * STAGE_ELEMS;
        const __nv_bfloat16* sAhi = base;
        const __nv_bfloat16* sAlo = base + A_MAT;
        const __nv_bfloat16* sBhi = base + 2 * A_MAT;
        const __nv_bfloat16* sBlo = base + 3 * A_MAT;

#pragma unroll
        for (int ks = 0; ks < 2; ks++) {
            const int kc = ks * 16 + kcol0;
            uint32_t af[4][4], bh[4][2], bl[4][2];
#pragma unroll
            for (int mi = 0; mi < 4; mi++) {
                const int r = arow0 + mi * 16;
                af[mi][0] = *(const uint32_t*)(sAhi + r * PAD + kc);
                af[mi][1] = *(const uint32_t*)(sAhi + (r + 8) * PAD + kc);
                af[mi][2] = *(const uint32_t*)(sAhi + r * PAD + kc + 8);
                af[mi][3] = *(const uint32_t*)(sAhi + (r + 8) * PAD + kc + 8);
            }
#pragma unroll
            for (int ni = 0; ni < 4; ni++) {
                const int r = brow0 + ni * 8;
                bh[ni][0] = *(const uint32_t*)(sBhi + r * PAD + kc);
                bh[ni][1] = *(const uint32_t*)(sBhi + r * PAD + kc + 8);
                bl[ni][0] = *(const uint32_t*)(sBlo + r * PAD + kc);
                bl[ni][1] = *(const uint32_t*)(sBlo + r * PAD + kc + 8);
            }
#pragma unroll
            for (int mi = 0; mi < 4; mi++)
#pragma unroll
                for (int ni = 0; ni < 4; ni++)
                    mma16816(acc[mi][ni], af[mi], bh[ni]);
#pragma unroll
            for (int mi = 0; mi < 4; mi++)
#pragma unroll
                for (int ni = 0; ni < 4; ni++)
                    mma16816(acc[mi][ni], af[mi], bl[ni]);
            // reload A as lo (overwrite hi frags)
#pragma unroll
            for (int mi = 0; mi < 4; mi++) {
                const int r = arow0 + mi * 16;
                af[mi][0] = *(const uint32_t*)(sAlo + r * PAD + kc);
                af[mi][1] = *(const uint32_t*)(sAlo + (r + 8) * PAD + kc);
                af[mi][2] = *(const uint32_t*)(sAlo + r * PAD + kc + 8);
                af[mi][3] = *(const uint32_t*)(sAlo + (r + 8) * PAD + kc + 8);
            }
#pragma unroll
            for (int mi = 0; mi < 4; mi++)
#pragma unroll
                for (int ni = 0; ni < 4; ni++)
                    mma16816(acc[mi][ni], af[mi], bh[ni]);
        }

        if (stage < 23) {
            store_smem((stage + 1) & 1);
            __syncthreads();
        }
    }

    // ---- Epilogue ----
    const int seg = (mode == 0) ? (n0 / CC) : 0;
    float* dstq = (seg == 0) ? g_q : ((seg == 1) ? g_k : g_v);

#pragma unroll
    for (int mi = 0; mi < 4; mi++) {
#pragma unroll
        for (int half = 0; half < 2; half++) {
            const int r = m0 + warp_m * 64 + mi * 16 + lr + half * 8;
#pragma unroll
            for (int ni = 0; ni < 4; ni++) {
                const int gc = n0 + warp_n * 32 + ni * 8 + lc * 2;
                float2 v;
                v.x = acc[mi][ni][half * 2 + 0] + bias[gc];
                v.y = acc[mi][ni][half * 2 + 1] + bias[gc + 1];
                if (mode == 0) {
                    const int bb = r >> 10, t = r & 1023;
                    const int cl = gc - seg * CC;
                    const int h = cl >> 6, d = cl & 63;
                    if (seg == 0) {
                        v.x *= 0.125f; v.y *= 0.125f;
                    } else if (seg == 1 && t > 0) {
                        float2 rv = *(const float2*)&rel[(size_t)(t - 1) * DD + d];
                        v.x += rv.x; v.y += rv.y;
                    }
                    *(float2*)&dstq[(((size_t)bb * HH + h) * TT + t) * DD + d] = v;
                } else {
                    *(float2*)&out[(size_t)r * CC + gc] = v;
                }
            }
        }
    }
}

// ---------------------------------------------------------------------------
// Causal flash attention, fp32 (unchanged from R1 — passed, ~470us).
// ---------------------------------------------------------------------------
struct FlashSmem {
    float Qt[64][68];
    float Kt[64][68];
    float Vs[64][64];
    float Pt[64][64];
    float red1[16][64];
    float red2[16][64];
    float ms[64];
    float ls[64];
    float fs[64];
};

__global__ __launch_bounds__(256, 2) void flash_kernel()
{
    extern __shared__ char smem_raw[];
    FlashSmem* S = reinterpret_cast<FlashSmem*>(smem_raw);

    const int it = gridDim.x - 1 - blockIdx.x;
    const int bh = blockIdx.y;
    const float* Qg = g_q + (size_t)bh * TT * DD;
    const float* Kg = g_k + (size_t)bh * TT * DD;
    const float* Vg = g_v + (size_t)bh * TT * DD;

    const int tid = threadIdx.x;
    const int tx = tid & 15, ty = tid >> 4;
    const int dg = tid & 15, jb = tid >> 4;

    {
        const float* qp = &Qg[(size_t)(it * 64 + jb * 4) * DD + dg * 4];
        float4 t0 = *(const float4*)(qp);
        float4 t1 = *(const float4*)(qp + DD);
        float4 t2 = *(const float4*)(qp + 2 * DD);
        float4 t3 = *(const float4*)(qp + 3 * DD);
        *(float4*)&S->Qt[dg * 4 + 0][jb * 4] = make_float4(t0.x, t1.x, t2.x, t3.x);
        *(float4*)&S->Qt[dg * 4 + 1][jb * 4] = make_float4(t0.y, t1.y, t2.y, t3.y);
        *(float4*)&S->Qt[dg * 4 + 2][jb * 4] = make_float4(t0.z, t1.z, t2.z, t3.z);
        *(float4*)&S->Qt[dg * 4 + 3][jb * 4] = make_float4(t0.w, t1.w, t2.w, t3.w);
    }
    if (tid < 64) { S->ms[tid] = -1e30f; S->ls[tid] = 0.f; }

    float o[4][4];
#pragma unroll
    for (int a = 0; a < 4; a++)
#pragma unroll
        for (int b = 0; b < 4; b++) o[a][b] = 0.f;
    __syncthreads();

    for (int jt = 0; jt <= it; jt++) {
        __syncthreads();
        {
            const float* kp = &Kg[(size_t)(jt * 64 + jb * 4) * DD + dg * 4];
            float4 t0 = *(const float4*)(kp);
            float4 t1 = *(const float4*)(kp + DD);
            float4 t2 = *(const float4*)(kp + 2 * DD);
            float4 t3 = *(const float4*)(kp + 3 * DD);
            *(float4*)&S->Kt[dg * 4 + 0][jb * 4] = make_float4(t0.x, t1.x, t2.x, t3.x);
            *(float4*)&S->Kt[dg * 4 + 1][jb * 4] = make_float4(t0.y, t1.y, t2.y, t3.y);
            *(float4*)&S->Kt[dg * 4 + 2][jb * 4] = make_float4(t0.z, t1.z, t2.z, t3.z);
            *(float4*)&S->Kt[dg * 4 + 3][jb * 4] = make_float4(t0.w, t1.w, t2.w, t3.w);
            const float* vp = &Vg[(size_t)(jt * 64 + jb * 4) * DD + dg * 4];
            *(float4*)&S->Vs[jb * 4 + 0][dg * 4] = *(const float4*)(vp);
            *(float4*)&S->Vs[jb * 4 + 1][dg * 4] = *(const float4*)(vp + DD);
            *(float4*)&S->Vs[jb * 4 + 2][dg * 4] = *(const float4*)(vp + 2 * DD);
            *(float4*)&S->Vs[jb * 4 + 3][dg * 4] = *(const float4*)(vp + 3 * DD);
        }
        __syncthreads();

        float st[4][4];
#pragma unroll
        for (int a = 0; a < 4; a++)
#pragma unroll
            for (int b = 0; b < 4; b++) st[a][b] = 0.f;
#pragma unroll 16
        for (int d = 0; d < 64; d++) {
            float4 rk = *(const float4*)&S->Kt[d][ty * 4];
            float4 rq = *(const float4*)&S->Qt[d][tx * 4];
            float ka[4] = {rk.x, rk.y, rk.z, rk.w};
            float qa[4] = {rq.x, rq.y, rq.z, rq.w};
#pragma unroll
            for (int a = 0; a < 4; a++)
#pragma unroll
                for (int b = 0; b < 4; b++)
                    st[a][b] += ka[a] * qa[b];
        }
        if (jt == it) {
#pragma unroll
            for (int a = 0; a < 4; a++)
#pragma unroll
                for (int b = 0; b < 4; b++)
                    if (ty * 4 + a > tx * 4 + b) st[a][b] = -1e30f;
        }

#pragma unroll
        for (int b = 0; b < 4; b++) {
            float m = fmaxf(fmaxf(st[0][b], st[1][b]), fmaxf(st[2][b], st[3][b]));
            S->red1[ty][tx * 4 + b] = m;
        }
        __syncthreads();

        float mnew[4];
#pragma unroll
        for (int b = 0; b < 4; b++) {
            float m = S->ms[tx * 4 + b];
#pragma unroll
            for (int yy = 0; yy < 16; yy++)
                m = fmaxf(m, S->red1[yy][tx * 4 + b]);
            mnew[b] = m;
        }

        float lsum[4] = {0.f, 0.f, 0.f, 0.f};
#pragma unroll
        for (int a = 0; a < 4; a++) {
            float p0 = __expf(st[a][0] - mnew[0]);
            float p1 = __expf(st[a][1] - mnew[1]);
            float p2 = __expf(st[a][2] - mnew[2]);
            float p3 = __expf(st[a][3] - mnew[3]);
            lsum[0] += p0; lsum[1] += p1; lsum[2] += p2; lsum[3] += p3;
            *(float4*)&S->Pt[ty * 4 + a][tx * 4] = make_float4(p0, p1, p2, p3);
        }
#pragma unroll
        for (int b = 0; b < 4; b++)
            S->red2[ty][tx * 4 + b] = lsum[b];
        __syncthreads();

        if (ty == 0) {
#pragma unroll
            for (int b = 0; b < 4; b++) {
                const int i = tx * 4 + b;
                float s = 0.f;
#pragma unroll
                for (int yy = 0; yy < 16; yy++) s += S->red2[yy][i];
                float f = __expf(S->ms[i] - mnew[b]);
                S->ls[i] = S->ls[i] * f + s;
                S->fs[i] = f;
                S->ms[i] = mnew[b];
            }
        }
        __syncthreads();

#pragma unroll
        for (int a = 0; a < 4; a++) {
            float f = S->fs[ty * 4 + a];
#pragma unroll
            for (int b = 0; b < 4; b++) o[a][b] *= f;
        }
#pragma unroll 16
        for (int j = 0; j < 64; j++) {
            float4 rp = *(const float4*)&S->Pt[j][ty * 4];
            float4 rv = *(const float4*)&S->Vs[j][tx * 4];
            float pa[4] = {rp.x, rp.y, rp.z, rp.w};
            float va[4] = {rv.x, rv.y, rv.z, rv.w};
#pragma unroll
            for (int a = 0; a < 4; a++)
#pragma unroll
                for (int b = 0; b < 4; b++)
                    o[a][b] += pa[a] * va[b];
        }
    }

    const int h = bh % HH, bb = bh / HH;
#pragma unroll
    for (int a = 0; a < 4; a++) {
        const int i = ty * 4 + a;
        const int tg = it * 64 + i;
        const float inv = 1.0f / S->ls[i];
        float4 ov = make_float4(o[a][0] * inv, o[a][1] * inv,
                                o[a][2] * inv, o[a][3] * inv);
        *(float4*)&g_y[((size_t)bb * TT + tg) * CC + h * DD + tx * 4] = ov;
    }
}

// ---------------------------------------------------------------------------
extern "C" void kernel_launch(void* const* d_in, const int* in_sizes, int n_in,
                              void* d_out, int out_size)
{
    const float* x      = (const float*)d_in[0];
    const float* w_attn = (const float*)d_in[1];
    const float* b_attn = (const float*)d_in[2];
    const float* w_proj = (const float*)d_in[3];
    const float* b_proj = (const float*)d_in[4];
    const float* rel    = (const float*)d_in[5];
    float* out = (float*)d_out;

    cudaFuncSetAttribute(tc_gemm_kernel,
                         cudaFuncAttributeMaxDynamicSharedMemorySize, GEMM_SMEM);
    cudaFuncSetAttribute(flash_kernel,
                         cudaFuncAttributeMaxDynamicSharedMemorySize,
                         (int)sizeof(FlashSmem));

    tc_gemm_kernel<<<dim3(N3 / 128, MR / 128), 256, GEMM_SMEM>>>(
        x, w_attn, b_attn, rel, nullptr, N3, 0);
    flash_kernel<<<dim3(TT / 64, BQ * HH), 256, sizeof(FlashSmem)>>>();
    tc_gemm_kernel<<<dim3(CC / 128, MR / 128), 256, GEMM_SMEM>>>(
        x, w_proj, b_proj, rel, out, CC, 1);
}

// round 5
// speedup vs baseline: 1.6964x; 1.2898x over previous
#include <cuda_runtime.h>
#include <cuda_bf16.h>
#include <cstdint>

#define BQ 8
#define TT 1024
#define CC 768
#define HH 12
#define DD 64
#define MR (BQ*TT)
#define N3 (3*CC)

// Scratch (allocation-free rule: __device__ globals)
__device__ float g_q[(size_t)BQ*HH*TT*DD];   // [B,H,T,D] pre-scaled
__device__ float g_k[(size_t)BQ*HH*TT*DD];   // [B,H,T,D] with rel' folded in
__device__ float g_v[(size_t)BQ*HH*TT*DD];   // [B,H,T,D]
__device__ float g_y[(size_t)BQ*TT*CC];      // [B,T,C] attention output

// ---------------------------------------------------------------------------
// mma.sync m16n8k16 bf16 -> f32 (HMMA; family-PTX safe)
// ---------------------------------------------------------------------------
__device__ __forceinline__ void mma16816(float* d, const uint32_t* a, const uint32_t* b) {
    asm volatile(
        "mma.sync.aligned.m16n8k16.row.col.f32.bf16.bf16.f32 "
        "{%0,%1,%2,%3}, {%4,%5,%6,%7}, {%8,%9}, {%0,%1,%2,%3};\n"
        : "+f"(d[0]), "+f"(d[1]), "+f"(d[2]), "+f"(d[3])
        : "r"(a[0]), "r"(a[1]), "r"(a[2]), "r"(a[3]), "r"(b[0]), "r"(b[1]));
}

struct __align__(8) BF4 { __nv_bfloat16 a, b, c, d; };

__device__ __forceinline__ void cvt_split(float x, __nv_bfloat16& h, __nv_bfloat16& l) {
    h = __float2bfloat16(x);
    l = __float2bfloat16(x - __bfloat162float(h));
}

// fast 2^y for y <= 0, FMA-pipe only (no MUFU). ~1.5e-5 max rel error.
__device__ __forceinline__ float exp2p(float y) {
    y = fmaxf(y, -126.f);
    float fi = floorf(y);
    float f = y - fi;
    float p = 1.f + f * (0.6931472f + f * (0.2402265f + f * (0.0555041f +
              f * (0.0096181f + f * (0.0013334f + f * 0.0001546f)))));
    return __int_as_float(__float_as_int(p) + ((int)fi << 23));
}

#define LOG2E 1.4426950408889634f

// ---------------------------------------------------------------------------
// Tensor-core GEMM (unchanged from R3 — passing): 128x128x32, bf16 hi/lo 3-pass
// ---------------------------------------------------------------------------
#define PAD 40
#define A_MAT (128 * PAD)
#define STAGE_ELEMS (4 * A_MAT)
#define GEMM_SMEM (2 * STAGE_ELEMS * 2)

__global__ __launch_bounds__(256, 1) void tc_gemm_kernel(
    const float* __restrict__ A_in, const float* __restrict__ W,
    const float* __restrict__ bias, const float* __restrict__ rel,
    float* __restrict__ out, int ldw, int mode)
{
    extern __shared__ __nv_bfloat16 sm[];

    const float* A = (mode == 0) ? A_in : g_y;

    const int tid = threadIdx.x;
    const int wid = tid >> 5, lane = tid & 31;
    const int n0 = blockIdx.x * 128;
    const int m0 = blockIdx.y * 128;

    const int warp_m = wid & 1;
    const int warp_n = wid >> 1;
    const int lr = lane >> 2;
    const int lc = lane & 3;

    const int am = tid >> 1;
    const int akq = (tid & 1) * 16;
    const int bk0 = (tid >> 5) * 4;
    const int bn0 = (tid & 31) * 4;

    const float* Ag = A + (size_t)(m0 + am) * CC + akq;
    const float* Wg = W + (size_t)bk0 * ldw + n0 + bn0;

    float acc[4][4][4];
#pragma unroll
    for (int i = 0; i < 4; i++)
#pragma unroll
        for (int j = 0; j < 4; j++)
#pragma unroll
            for (int r = 0; r < 4; r++) acc[i][j][r] = 0.f;

    float4 pa[4];
    float4 pb[4];

    auto load_global = [&](int k0) {
#pragma unroll
        for (int c = 0; c < 4; c++)
            pa[c] = *(const float4*)(Ag + k0 + c * 4);
#pragma unroll
        for (int i = 0; i < 4; i++)
            pb[i] = *(const float4*)(Wg + (size_t)(k0 + i) * ldw);
    };

    auto store_smem = [&](int s) {
        __nv_bfloat16* base = sm + s * STAGE_ELEMS;
        __nv_bfloat16* sAhi = base;
        __nv_bfloat16* sAlo = base + A_MAT;
        __nv_bfloat16* sBhi = base + 2 * A_MAT;
        __nv_bfloat16* sBlo = base + 3 * A_MAT;
#pragma unroll
        for (int c = 0; c < 4; c++) {
            BF4 h, l;
            cvt_split(pa[c].x, h.a, l.a);
            cvt_split(pa[c].y, h.b, l.b);
            cvt_split(pa[c].z, h.c, l.c);
            cvt_split(pa[c].w, h.d, l.d);
            const int off = am * PAD + akq + c * 4;
            *(BF4*)(sAhi + off) = h;
            *(BF4*)(sAlo + off) = l;
        }
        float col[4][4] = {
            {pb[0].x, pb[1].x, pb[2].x, pb[3].x},
            {pb[0].y, pb[1].y, pb[2].y, pb[3].y},
            {pb[0].z, pb[1].z, pb[2].z, pb[3].z},
            {pb[0].w, pb[1].w, pb[2].w, pb[3].w}};
#pragma unroll
        for (int j = 0; j < 4; j++) {
            BF4 h, l;
            cvt_split(col[j][0], h.a, l.a);
            cvt_split(col[j][1], h.b, l.b);
            cvt_split(col[j][2], h.c, l.c);
            cvt_split(col[j][3], h.d, l.d);
            const int off = (bn0 + j) * PAD + bk0;
            *(BF4*)(sBhi + off) = h;
            *(BF4*)(sBlo + off) = l;
        }
    };

    load_global(0);
    store_smem(0);
    __syncthreads();

    const int arow0 = warp_m * 64 + lr;
    const int brow0 = warp_n * 32 + lr;
    const int kcol0 = lc * 2;

    for (int stage = 0; stage < 24; stage++) {
        if (stage < 23) load_global((stage + 1) * 32);

        const __nv_bfloat16* base = sm + (stage & 1) * STAGE_ELEMS;
        const __nv_bfloat16* sAhi = base;
        const __nv_bfloat16* sAlo = base + A_MAT;
        const __nv_bfloat16* sBhi = base + 2 * A_MAT;
        const __nv_bfloat16* sBlo = base + 3 * A_MAT;

#pragma unroll
        for (int ks = 0; ks < 2; ks++) {
            const int kc = ks * 16 + kcol0;
            uint32_t af[4][4], bh[4][2], bl[4][2];
#pragma unroll
            for (int mi = 0; mi < 4; mi++) {
                const int r = arow0 + mi * 16;
                af[mi][0] = *(const uint32_t*)(sAhi + r * PAD + kc);
                af[mi][1] = *(const uint32_t*)(sAhi + (r + 8) * PAD + kc);
                af[mi][2] = *(const uint32_t*)(sAhi + r * PAD + kc + 8);
                af[mi][3] = *(const uint32_t*)(sAhi + (r + 8) * PAD + kc + 8);
            }
#pragma unroll
            for (int ni = 0; ni < 4; ni++) {
                const int r = brow0 + ni * 8;
                bh[ni][0] = *(const uint32_t*)(sBhi + r * PAD + kc);
                bh[ni][1] = *(const uint32_t*)(sBhi + r * PAD + kc + 8);
                bl[ni][0] = *(const uint32_t*)(sBlo + r * PAD + kc);
                bl[ni][1] = *(const uint32_t*)(sBlo + r * PAD + kc + 8);
            }
#pragma unroll
            for (int mi = 0; mi < 4; mi++)
#pragma unroll
                for (int ni = 0; ni < 4; ni++)
                    mma16816(acc[mi][ni], af[mi], bh[ni]);
#pragma unroll
            for (int mi = 0; mi < 4; mi++)
#pragma unroll
                for (int ni = 0; ni < 4; ni++)
                    mma16816(acc[mi][ni], af[mi], bl[ni]);
#pragma unroll
            for (int mi = 0; mi < 4; mi++) {
                const int r = arow0 + mi * 16;
                af[mi][0] = *(const uint32_t*)(sAlo + r * PAD + kc);
                af[mi][1] = *(const uint32_t*)(sAlo + (r + 8) * PAD + kc);
                af[mi][2] = *(const uint32_t*)(sAlo + r * PAD + kc + 8);
                af[mi][3] = *(const uint32_t*)(sAlo + (r + 8) * PAD + kc + 8);
            }
#pragma unroll
            for (int mi = 0; mi < 4; mi++)
#pragma unroll
                for (int ni = 0; ni < 4; ni++)
                    mma16816(acc[mi][ni], af[mi], bh[ni]);
        }

        if (stage < 23) {
            store_smem((stage + 1) & 1);
            __syncthreads();
        }
    }

    const int seg = (mode == 0) ? (n0 / CC) : 0;
    float* dstq = (seg == 0) ? g_q : ((seg == 1) ? g_k : g_v);

#pragma unroll
    for (int mi = 0; mi < 4; mi++) {
#pragma unroll
        for (int half = 0; half < 2; half++) {
            const int r = m0 + warp_m * 64 + mi * 16 + lr + half * 8;
#pragma unroll
            for (int ni = 0; ni < 4; ni++) {
                const int gc = n0 + warp_n * 32 + ni * 8 + lc * 2;
                float2 v;
                v.x = acc[mi][ni][half * 2 + 0] + bias[gc];
                v.y = acc[mi][ni][half * 2 + 1] + bias[gc + 1];
                if (mode == 0) {
                    const int bb = r >> 10, t = r & 1023;
                    const int cl = gc - seg * CC;
                    const int h = cl >> 6, d = cl & 63;
                    if (seg == 0) {
                        v.x *= 0.125f; v.y *= 0.125f;
                    } else if (seg == 1 && t > 0) {
                        float2 rv = *(const float2*)&rel[(size_t)(t - 1) * DD + d];
                        v.x += rv.x; v.y += rv.y;
                    }
                    *(float2*)&dstq[(((size_t)bb * HH + h) * TT + t) * DD + d] = v;
                } else {
                    *(float2*)&out[(size_t)r * CC + gc] = v;
                }
            }
        }
    }
}

// ---------------------------------------------------------------------------
// HMMA causal flash attention. BR=BC=64, 128 threads (4 warps, m16 each).
// S = Qh/Ql x Kh/Kl 3-pass split; softmax in registers (quad shuffles,
// poly exp2); PV = Ph/Pl x Vh/Vl 3-pass split (fixes R4's 2e-3 error).
// ---------------------------------------------------------------------------
#define FPAD 72

struct FlashSmem {
    __nv_bfloat16 Qh[64][FPAD], Ql[64][FPAD];
    __nv_bfloat16 Kh[64][FPAD], Kl[64][FPAD];
    __nv_bfloat16 Vh[64][FPAD], Vl[64][FPAD];   // V^T hi/lo: [d][j]
};

__global__ __launch_bounds__(128, 2) void flash_kernel()
{
    extern __shared__ char fsm_raw[];
    FlashSmem* S = reinterpret_cast<FlashSmem*>(fsm_raw);

    const int it = gridDim.x - 1 - blockIdx.x;   // heaviest first
    const int bh = blockIdx.y;
    const float* Qg = g_q + (size_t)bh * TT * DD;
    const float* Kg = g_k + (size_t)bh * TT * DD;
    const float* Vg = g_v + (size_t)bh * TT * DD;

    const int tid = threadIdx.x;
    const int warp = tid >> 5, lane = tid & 31;
    const int lr = lane >> 2, lc = lane & 3;

    // ---- Load Q tile (rows it*64..), split hi/lo ----
#pragma unroll
    for (int b = 0; b < 8; b++) {
        const int qi = tid + b * 128;
        const int row = qi >> 4, c4 = (qi & 15) * 4;
        float4 v = *(const float4*)(Qg + (size_t)(it * 64 + row) * DD + c4);
        BF4 h, l;
        cvt_split(v.x, h.a, l.a);
        cvt_split(v.y, h.b, l.b);
        cvt_split(v.z, h.c, l.c);
        cvt_split(v.w, h.d, l.d);
        *(BF4*)&S->Qh[row][c4] = h;
        *(BF4*)&S->Ql[row][c4] = l;
    }
    __syncthreads();

    // ---- Q fragments in registers (invariant) ----
    uint32_t qh[4][4], ql[4][4];
    const int qr = warp * 16 + lr;
#pragma unroll
    for (int t = 0; t < 4; t++) {
        const int kc = t * 16 + lc * 2;
        qh[t][0] = *(const uint32_t*)&S->Qh[qr][kc];
        qh[t][1] = *(const uint32_t*)&S->Qh[qr + 8][kc];
        qh[t][2] = *(const uint32_t*)&S->Qh[qr][kc + 8];
        qh[t][3] = *(const uint32_t*)&S->Qh[qr + 8][kc + 8];
        ql[t][0] = *(const uint32_t*)&S->Ql[qr][kc];
        ql[t][1] = *(const uint32_t*)&S->Ql[qr + 8][kc];
        ql[t][2] = *(const uint32_t*)&S->Ql[qr][kc + 8];
        ql[t][3] = *(const uint32_t*)&S->Ql[qr + 8][kc + 8];
    }

    float o[8][4];
#pragma unroll
    for (int nt = 0; nt < 8; nt++)
#pragma unroll
        for (int r = 0; r < 4; r++) o[nt][r] = 0.f;
    float m_run[2] = {-1e30f, -1e30f};
    float l_run[2] = {0.f, 0.f};

    for (int jt = 0; jt <= it; jt++) {
        __syncthreads();
        // ---- Load K (split) and V (transposed, split) ----
#pragma unroll
        for (int b = 0; b < 8; b++) {
            const int qi = tid + b * 128;
            const int row = qi >> 4, c4 = (qi & 15) * 4;
            float4 v = *(const float4*)(Kg + (size_t)(jt * 64 + row) * DD + c4);
            BF4 h, l;
            cvt_split(v.x, h.a, l.a);
            cvt_split(v.y, h.b, l.b);
            cvt_split(v.z, h.c, l.c);
            cvt_split(v.w, h.d, l.d);
            *(BF4*)&S->Kh[row][c4] = h;
            *(BF4*)&S->Kl[row][c4] = l;
        }
#pragma unroll
        for (int b = 0; b < 2; b++) {
            const int bi = tid + b * 128;
            const int jr = (bi >> 4) * 4, dc = (bi & 15) * 4;
            const float* vp = Vg + (size_t)(jt * 64 + jr) * DD + dc;
            float4 r0 = *(const float4*)(vp);
            float4 r1 = *(const float4*)(vp + DD);
            float4 r2 = *(const float4*)(vp + 2 * DD);
            float4 r3 = *(const float4*)(vp + 3 * DD);
            float col[4][4] = {
                {r0.x, r1.x, r2.x, r3.x},
                {r0.y, r1.y, r2.y, r3.y},
                {r0.z, r1.z, r2.z, r3.z},
                {r0.w, r1.w, r2.w, r3.w}};
#pragma unroll
            for (int j = 0; j < 4; j++) {
                BF4 h, l;
                cvt_split(col[j][0], h.a, l.a);
                cvt_split(col[j][1], h.b, l.b);
                cvt_split(col[j][2], h.c, l.c);
                cvt_split(col[j][3], h.d, l.d);
                *(BF4*)&S->Vh[dc + j][jr] = h;
                *(BF4*)&S->Vl[dc + j][jr] = l;
            }
        }
        __syncthreads();

        // ---- S = Q K^T (3-pass split) ----
        float s[8][4];
#pragma unroll
        for (int nt = 0; nt < 8; nt++)
#pragma unroll
            for (int r = 0; r < 4; r++) s[nt][r] = 0.f;
#pragma unroll
        for (int nt = 0; nt < 8; nt++) {
            const int kr = nt * 8 + lr;
#pragma unroll
            for (int t = 0; t < 4; t++) {
                const int kc = t * 16 + lc * 2;
                uint32_t bhf[2], blf[2];
                bhf[0] = *(const uint32_t*)&S->Kh[kr][kc];
                bhf[1] = *(const uint32_t*)&S->Kh[kr][kc + 8];
                blf[0] = *(const uint32_t*)&S->Kl[kr][kc];
                blf[1] = *(const uint32_t*)&S->Kl[kr][kc + 8];
                mma16816(s[nt], qh[t], bhf);
                mma16816(s[nt], qh[t], blf);
                mma16816(s[nt], ql[t], bhf);
            }
        }

        // ---- causal mask on diagonal tile ----
        if (jt == it) {
#pragma unroll
            for (int nt = 0; nt < 8; nt++) {
#pragma unroll
                for (int r = 0; r < 4; r++) {
                    const int col = nt * 8 + lc * 2 + (r & 1);
                    const int row = warp * 16 + lr + ((r >> 1) * 8);
                    if (col > row) s[nt][r] = -1e30f;
                }
            }
        }

        // ---- row max (2 rows per thread), quad shuffle reduce ----
        float mnew[2], fscale[2];
#pragma unroll
        for (int h = 0; h < 2; h++) {
            float m = -1e30f;
#pragma unroll
            for (int nt = 0; nt < 8; nt++)
                m = fmaxf(m, fmaxf(s[nt][h * 2], s[nt][h * 2 + 1]));
            m = fmaxf(m, __shfl_xor_sync(0xFFFFFFFF, m, 1));
            m = fmaxf(m, __shfl_xor_sync(0xFFFFFFFF, m, 2));
            mnew[h] = fmaxf(m_run[h], m);
            fscale[h] = exp2p((m_run[h] - mnew[h]) * LOG2E);
            m_run[h] = mnew[h];
        }

        // ---- p = exp(s - m), row sums ----
        float rsum[2] = {0.f, 0.f};
#pragma unroll
        for (int nt = 0; nt < 8; nt++) {
#pragma unroll
            for (int r = 0; r < 4; r++) {
                const int h = r >> 1;
                float p = exp2p((s[nt][r] - mnew[h]) * LOG2E);
                s[nt][r] = p;
                rsum[h] += p;
            }
        }
#pragma unroll
        for (int h = 0; h < 2; h++) {
            rsum[h] += __shfl_xor_sync(0xFFFFFFFF, rsum[h], 1);
            rsum[h] += __shfl_xor_sync(0xFFFFFFFF, rsum[h], 2);
            l_run[h] = l_run[h] * fscale[h] + rsum[h];
        }

        // ---- rescale O ----
#pragma unroll
        for (int nt = 0; nt < 8; nt++) {
#pragma unroll
            for (int r = 0; r < 4; r++) o[nt][r] *= fscale[r >> 1];
        }

        // ---- pack P hi/lo fragments (acc layout == A-frag layout) ----
        uint32_t pfh[4][4], pfl[4][4];
#pragma unroll
        for (int t = 0; t < 4; t++) {
#pragma unroll
            for (int half = 0; half < 2; half++) {
                const float v0 = s[2 * t + (half >> 1)][0];  // placeholder, rewritten below
            }
            __nv_bfloat16 h00, l00, h01, l01, h10, l10, h11, l11;
            cvt_split(s[2 * t][0], h00, l00);
            cvt_split(s[2 * t][1], h01, l01);
            __nv_bfloat162 ph0 = {h00, h01}, pl0 = {l00, l01};
            cvt_split(s[2 * t][2], h10, l10);
            cvt_split(s[2 * t][3], h11, l11);
            __nv_bfloat162 ph1 = {h10, h11}, pl1 = {l10, l11};
            __nv_bfloat16 h20, l20, h21, l21, h30, l30, h31, l31;
            cvt_split(s[2 * t + 1][0], h20, l20);
            cvt_split(s[2 * t + 1][1], h21, l21);
            __nv_bfloat162 ph2 = {h20, h21}, pl2 = {l20, l21};
            cvt_split(s[2 * t + 1][2], h30, l30);
            cvt_split(s[2 * t + 1][3], h31, l31);
            __nv_bfloat162 ph3 = {h30, h31}, pl3 = {l30, l31};
            pfh[t][0] = *(uint32_t*)&ph0;
            pfh[t][1] = *(uint32_t*)&ph1;
            pfh[t][2] = *(uint32_t*)&ph2;
            pfh[t][3] = *(uint32_t*)&ph3;
            pfl[t][0] = *(uint32_t*)&pl0;
            pfl[t][1] = *(uint32_t*)&pl1;
            pfl[t][2] = *(uint32_t*)&pl2;
            pfl[t][3] = *(uint32_t*)&pl3;
        }

        // ---- O += P V (3-pass split) ----
#pragma unroll
        for (int dt = 0; dt < 8; dt++) {
            const int vr = dt * 8 + lr;
#pragma unroll
            for (int t = 0; t < 4; t++) {
                const int jc = t * 16 + lc * 2;
                uint32_t bhf[2], blf[2];
                bhf[0] = *(const uint32_t*)&S->Vh[vr][jc];
                bhf[1] = *(const uint32_t*)&S->Vh[vr][jc + 8];
                blf[0] = *(const uint32_t*)&S->Vl[vr][jc];
                blf[1] = *(const uint32_t*)&S->Vl[vr][jc + 8];
                mma16816(o[dt], pfh[t], bhf);
                mma16816(o[dt], pfh[t], blf);
                mma16816(o[dt], pfl[t], bhf);
            }
        }
    }

    // ---- Output: y[b, t, h*64 + d] = o / l ----
    const int hh = bh % HH, bb = bh / HH;
    const float inv0 = 1.0f / l_run[0];
    const float inv1 = 1.0f / l_run[1];
    const int row0 = it * 64 + warp * 16 + lr;
#pragma unroll
    for (int nt = 0; nt < 8; nt++) {
        const int d = nt * 8 + lc * 2;
        float2 v0 = make_float2(o[nt][0] * inv0, o[nt][1] * inv0);
        float2 v1 = make_float2(o[nt][2] * inv1, o[nt][3] * inv1);
        *(float2*)&g_y[((size_t)bb * TT + row0) * CC + hh * DD + d] = v0;
        *(float2*)&g_y[((size_t)bb * TT + row0 + 8) * CC + hh * DD + d] = v1;
    }
}

// ---------------------------------------------------------------------------
extern "C" void kernel_launch(void* const* d_in, const int* in_sizes, int n_in,
                              void* d_out, int out_size)
{
    const float* x      = (const float*)d_in[0];
    const float* w_attn = (const float*)d_in[1];
    const float* b_attn = (const float*)d_in[2];
    const float* w_proj = (const float*)d_in[3];
    const float* b_proj = (const float*)d_in[4];
    const float* rel    = (const float*)d_in[5];
    float* out = (float*)d_out;

    cudaFuncSetAttribute(tc_gemm_kernel,
                         cudaFuncAttributeMaxDynamicSharedMemorySize, GEMM_SMEM);
    cudaFuncSetAttribute(flash_kernel,
                         cudaFuncAttributeMaxDynamicSharedMemorySize,
                         (int)sizeof(FlashSmem));

    tc_gemm_kernel<<<dim3(N3 / 128, MR / 128), 256, GEMM_SMEM>>>(
        x, w_attn, b_attn, rel, nullptr, N3, 0);
    flash_kernel<<<dim3(TT / 64, BQ * HH), 128, sizeof(FlashSmem)>>>();
    tc_gemm_kernel<<<dim3(CC / 128, MR / 128), 256, GEMM_SMEM>>>(
        x, w_proj, b_proj, rel, out, CC, 1);
}